// round 5
// baseline (speedup 1.0000x reference)
#include <cuda_runtime.h>
#include <cuda_bf16.h>
#include <cstdint>

// ---------------------------------------------------------------------------
// Problem constants
// ---------------------------------------------------------------------------
#define BB      2
#define SS      2048
#define HIDDEN  2048
#define NH      8
#define NKV     1
#define HD      256
#define INTER   16384
#define MTOK    (BB*SS)          // 4096 tokens

// ---------------------------------------------------------------------------
// Scratch (device globals; allocation inside kernel_launch is forbidden)
// ---------------------------------------------------------------------------
__device__ float g_h   [(size_t)MTOK * HIDDEN];          // normed hidden (ln1)
__device__ float g_q   [(size_t)MTOK * NH * HD];         // xq [b,s,h,d]
__device__ float g_k   [(size_t)MTOK * NKV * HD];        // xk [b,s,d]
__device__ float g_v   [(size_t)MTOK * NKV * HD];        // xv [b,s,d]
__device__ float g_vt  [(size_t)BB * HD * SS];           // v transposed [b,d,c]
__device__ float g_sc  [(size_t)BB * NH * SS * SS];      // scores/probs  (268MB)
__device__ float g_attn[(size_t)MTOK * NH * HD];         // attn out [b,s,h,d]
__device__ float g_h2  [(size_t)MTOK * HIDDEN];          // hidden after attn+res
__device__ float g_h3  [(size_t)MTOK * HIDDEN];          // normed hidden (ln2)
__device__ float g_gate[(size_t)MTOK * INTER];           // gate (then gelu*up)
__device__ float g_up  [(size_t)MTOK * INTER];           // up

// ---------------------------------------------------------------------------
// TF32 helpers
// ---------------------------------------------------------------------------
__device__ __forceinline__ unsigned f2tf(float x) {
    unsigned u;
    asm("cvt.rna.tf32.f32 %0, %1;" : "=r"(u) : "f"(x));
    return u;
}

__device__ __forceinline__ void stage4(float* p, float4 v) {
    p[0] = __uint_as_float(f2tf(v.x));
    p[1] = __uint_as_float(f2tf(v.y));
    p[2] = __uint_as_float(f2tf(v.z));
    p[3] = __uint_as_float(f2tf(v.w));
}

// ---------------------------------------------------------------------------
// TF32 tensor-core NT GEMM:  C[m,n] = alpha * sum_k A[m,k]*B[n,k]  (+ addsrc)
// Tiles: 128x128x16, 256 threads (8 warps in 2x4 grid, 64x32 warp tile),
// mma.sync m16n8k8 tf32, double-buffered smem. All dims divide tiles exactly.
// Batched via blockIdx.z = zb*zInner + zh with independent strides.
// ---------------------------------------------------------------------------
#define GBM 128
#define GBN 128
#define GBK 16
#define GLD (GBK + 4)   // smem row stride (20 floats) -> conflict-free frag loads

__global__ __launch_bounds__(256) void gemm_tf32_nt(
    const float* __restrict__ A, const float* __restrict__ B,
    float* __restrict__ C, const float* __restrict__ addsrc,
    int K, int lda, int ldb, int ldc,
    long long sAb, long long sAh,
    long long sBb, long long sBh,
    long long sCb, long long sCh,
    int zInner, float alpha)
{
    __shared__ __align__(16) float As[2][GBM][GLD];
    __shared__ __align__(16) float Bs[2][GBN][GLD];

    const int zb = blockIdx.z / zInner;
    const int zh = blockIdx.z % zInner;
    const float* Ab = A + zb * sAb + zh * sAh;
    const float* Bb = B + zb * sBb + zh * sBh;
    float*       Cb = C + zb * sCb + zh * sCh;
    const float* Db = addsrc ? (addsrc + zb * sCb + zh * sCh) : nullptr;

    const int m0  = blockIdx.y * GBM;
    const int n0  = blockIdx.x * GBN;
    const int tid = threadIdx.x;

    // Global loaders: 2 float4 per thread per matrix per k-tile
    const int lr = tid >> 2;           // 0..63
    const int lc = (tid & 3) << 2;     // 0,4,8,12
    const float* Ap0 = Ab + (long long)(m0 + lr) * lda + lc;
    const float* Ap1 = Ab + (long long)(m0 + lr + 64) * lda + lc;
    const float* Bp0 = Bb + (long long)(n0 + lr) * ldb + lc;
    const float* Bp1 = Bb + (long long)(n0 + lr + 64) * ldb + lc;

    const int lane = tid & 31, warp = tid >> 5;
    const int wm = (warp >> 2) * 64;   // 0 / 64
    const int wn = (warp & 3) * 32;    // 0..96
    const int g  = lane >> 2, t4 = lane & 3;

    float acc[4][4][4];
#pragma unroll
    for (int i = 0; i < 4; i++)
#pragma unroll
        for (int j = 0; j < 4; j++)
#pragma unroll
            for (int r = 0; r < 4; r++) acc[i][j][r] = 0.f;

    const int nk = K / GBK;

    // prologue: tile 0 -> regs -> smem[0]
    float4 ra0 = *(const float4*)Ap0;
    float4 ra1 = *(const float4*)Ap1;
    float4 rb0 = *(const float4*)Bp0;
    float4 rb1 = *(const float4*)Bp1;
    stage4(&As[0][lr][lc], ra0);
    stage4(&As[0][lr + 64][lc], ra1);
    stage4(&Bs[0][lr][lc], rb0);
    stage4(&Bs[0][lr + 64][lc], rb1);

    int buf = 0;
    for (int t = 0; t < nk; ++t) {
        __syncthreads();
        const bool more = (t + 1 < nk);
        if (more) {
            const int ko = (t + 1) * GBK;
            ra0 = *(const float4*)(Ap0 + ko);
            ra1 = *(const float4*)(Ap1 + ko);
            rb0 = *(const float4*)(Bp0 + ko);
            rb1 = *(const float4*)(Bp1 + ko);
        }

#pragma unroll
        for (int kk = 0; kk < GBK; kk += 8) {
            unsigned af[4][4];
            unsigned bf[4][2];
#pragma unroll
            for (int mi = 0; mi < 4; mi++) {
                const int r = wm + mi * 16 + g;
                af[mi][0] = __float_as_uint(As[buf][r][kk + t4]);
                af[mi][1] = __float_as_uint(As[buf][r + 8][kk + t4]);
                af[mi][2] = __float_as_uint(As[buf][r][kk + t4 + 4]);
                af[mi][3] = __float_as_uint(As[buf][r + 8][kk + t4 + 4]);
            }
#pragma unroll
            for (int ni = 0; ni < 4; ni++) {
                const int c = wn + ni * 8 + g;
                bf[ni][0] = __float_as_uint(Bs[buf][c][kk + t4]);
                bf[ni][1] = __float_as_uint(Bs[buf][c][kk + t4 + 4]);
            }
#pragma unroll
            for (int mi = 0; mi < 4; mi++)
#pragma unroll
                for (int ni = 0; ni < 4; ni++)
                    asm volatile(
                        "mma.sync.aligned.m16n8k8.row.col.f32.tf32.tf32.f32 "
                        "{%0,%1,%2,%3},{%4,%5,%6,%7},{%8,%9},{%0,%1,%2,%3};"
                        : "+f"(acc[mi][ni][0]), "+f"(acc[mi][ni][1]),
                          "+f"(acc[mi][ni][2]), "+f"(acc[mi][ni][3])
                        : "r"(af[mi][0]), "r"(af[mi][1]), "r"(af[mi][2]), "r"(af[mi][3]),
                          "r"(bf[ni][0]), "r"(bf[ni][1]));
        }

        if (more) {
            stage4(&As[buf ^ 1][lr][lc], ra0);
            stage4(&As[buf ^ 1][lr + 64][lc], ra1);
            stage4(&Bs[buf ^ 1][lr][lc], rb0);
            stage4(&Bs[buf ^ 1][lr + 64][lc], rb1);
        }
        buf ^= 1;
    }

    // epilogue
#pragma unroll
    for (int mi = 0; mi < 4; mi++) {
#pragma unroll
        for (int ni = 0; ni < 4; ni++) {
            const int row = m0 + wm + mi * 16 + g;
            const int col = n0 + wn + ni * 8 + 2 * t4;
            const long long o1 = (long long)row * ldc + col;
            const long long o2 = o1 + (long long)8 * ldc;
            float v0 = alpha * acc[mi][ni][0];
            float v1 = alpha * acc[mi][ni][1];
            float v2 = alpha * acc[mi][ni][2];
            float v3 = alpha * acc[mi][ni][3];
            if (Db) {
                v0 += Db[o1]; v1 += Db[o1 + 1];
                v2 += Db[o2]; v3 += Db[o2 + 1];
            }
            Cb[o1] = v0; Cb[o1 + 1] = v1;
            Cb[o2] = v2; Cb[o2 + 1] = v3;
        }
    }
}

// ---------------------------------------------------------------------------
// RMSNorm: one block per row of 2048
// ---------------------------------------------------------------------------
__global__ __launch_bounds__(256) void rmsnorm_kernel(
    const float* __restrict__ x, const float* __restrict__ w,
    float* __restrict__ o)
{
    const long long row = blockIdx.x;
    const float* xr = x + row * HIDDEN;
    float* orow = o + row * HIDDEN;

    float ss = 0.f;
    for (int i = threadIdx.x; i < HIDDEN; i += 256) {
        const float v = xr[i];
        ss = fmaf(v, v, ss);
    }
#pragma unroll
    for (int off = 16; off; off >>= 1) ss += __shfl_xor_sync(~0u, ss, off);

    __shared__ float sred[8];
    const int wi = threadIdx.x >> 5, li = threadIdx.x & 31;
    if (li == 0) sred[wi] = ss;
    __syncthreads();
    float tot = 0.f;
#pragma unroll
    for (int i = 0; i < 8; i++) tot += sred[i];

    const float rs = rsqrtf(tot * (1.0f / HIDDEN) + 1e-6f);
    for (int i = threadIdx.x; i < HIDDEN; i += 256)
        orow[i] = xr[i] * rs * (1.0f + w[i]);
}

// ---------------------------------------------------------------------------
// RoPE (in place): x [B,S,nheads,256] split 128/128
// ---------------------------------------------------------------------------
__global__ void rope_kernel(float* __restrict__ x,
                            const float* __restrict__ cs,
                            const float* __restrict__ sn,
                            int nheads, long long total)
{
    const long long idx = (long long)blockIdx.x * blockDim.x + threadIdx.x;
    if (idx >= total) return;
    const int i = (int)(idx & 127);
    const long long t = idx >> 7;            // b*S*nheads + s*nheads + h
    const int h = (int)(t % nheads);
    const long long bs = t / nheads;         // b*S + s
    const int s = (int)(bs & (SS - 1));
    const float c = cs[s * 128 + i];
    const float si = sn[s * 128 + i];
    float* p = x + (bs * nheads + h) * HD;
    const float x1 = p[i];
    const float x2 = p[i + 128];
    p[i]       = x1 * c - x2 * si;
    p[i + 128] = x1 * si + x2 * c;
}

// ---------------------------------------------------------------------------
// Transpose V: [b, c(2048), d(256)] -> [b, d, c]
// ---------------------------------------------------------------------------
__global__ void transpose_v_kernel(const float* __restrict__ v,
                                   float* __restrict__ vt)
{
    __shared__ float tile[32][33];
    const int b = blockIdx.z;
    const int c0 = blockIdx.x * 32;
    const int d0 = blockIdx.y * 32;
    const float* vb = v + (long long)b * SS * HD;
    float* vtb = vt + (long long)b * HD * SS;
    const int tx = threadIdx.x, ty = threadIdx.y;
    tile[ty][tx] = vb[(long long)(c0 + ty) * HD + d0 + tx];
    __syncthreads();
    vtb[(long long)(d0 + ty) * SS + c0 + tx] = tile[tx][ty];
}

// ---------------------------------------------------------------------------
// Causal softmax over rows of [B*H, S, S]. Masked (j>s) -> exact 0, matching
// the reference (-1e9 additive mask underflows exp to 0 in fp32).
// ---------------------------------------------------------------------------
__global__ __launch_bounds__(256) void softmax_causal_kernel(float* __restrict__ sc)
{
    const long long rowid = blockIdx.x;            // 0 .. B*H*S-1
    const int s = (int)(rowid & (SS - 1));
    float* row = sc + rowid * SS;
    const int n = s + 1;

    float mx = -3.4e38f;
    for (int i = threadIdx.x; i < n; i += 256) mx = fmaxf(mx, row[i]);
#pragma unroll
    for (int off = 16; off; off >>= 1) mx = fmaxf(mx, __shfl_xor_sync(~0u, mx, off));

    __shared__ float sm[8], ssum[8];
    const int wi = threadIdx.x >> 5, li = threadIdx.x & 31;
    if (li == 0) sm[wi] = mx;
    __syncthreads();
    float m2 = -3.4e38f;
#pragma unroll
    for (int i = 0; i < 8; i++) m2 = fmaxf(m2, sm[i]);

    float sum = 0.f;
    for (int i = threadIdx.x; i < n; i += 256) sum += __expf(row[i] - m2);
#pragma unroll
    for (int off = 16; off; off >>= 1) sum += __shfl_xor_sync(~0u, sum, off);
    if (li == 0) ssum[wi] = sum;
    __syncthreads();
    float tot = 0.f;
#pragma unroll
    for (int i = 0; i < 8; i++) tot += ssum[i];
    const float inv = 1.0f / tot;

    for (int i = threadIdx.x; i < SS; i += 256)
        row[i] = (i < n) ? __expf(row[i] - m2) * inv : 0.f;
}

// ---------------------------------------------------------------------------
// gate = gelu_tanh(gate) * up
// ---------------------------------------------------------------------------
__global__ void gelumul_kernel(float* __restrict__ gate,
                               const float* __restrict__ up,
                               long long total)
{
    const long long i = (long long)blockIdx.x * blockDim.x + threadIdx.x;
    if (i >= total) return;
    const float x = gate[i];
    const float x3 = x * x * x;
    const float t = tanhf(0.7978845608028654f * (x + 0.044715f * x3));
    gate[i] = 0.5f * x * (1.0f + t) * up[i];
}

// ---------------------------------------------------------------------------
// Launch
// ---------------------------------------------------------------------------
extern "C" void kernel_launch(void* const* d_in, const int* in_sizes, int n_in,
                              void* d_out, int out_size)
{
    (void)in_sizes; (void)n_in; (void)out_size;

    const float* hidden = (const float*)d_in[0];
    const float* fcos   = (const float*)d_in[1];
    const float* fsin   = (const float*)d_in[2];
    // d_in[3] kv_write_indices (= arange), d_in[4] k_cache (zeros, fully
    // overwritten), d_in[5] v_cache, d_in[6] mask (= causal -1e9): unused.
    const float* q_w    = (const float*)d_in[7];
    const float* k_w    = (const float*)d_in[8];
    const float* v_w    = (const float*)d_in[9];
    const float* o_w    = (const float*)d_in[10];
    const float* gate_w = (const float*)d_in[11];
    const float* up_w   = (const float*)d_in[12];
    const float* down_w = (const float*)d_in[13];
    const float* ln1    = (const float*)d_in[14];
    const float* ln2    = (const float*)d_in[15];
    float* out = (float*)d_out;

    float *h, *q, *k, *v, *vt, *sc, *attn, *h2, *h3, *gbuf, *ubuf;
    cudaGetSymbolAddress((void**)&h,    g_h);
    cudaGetSymbolAddress((void**)&q,    g_q);
    cudaGetSymbolAddress((void**)&k,    g_k);
    cudaGetSymbolAddress((void**)&v,    g_v);
    cudaGetSymbolAddress((void**)&vt,   g_vt);
    cudaGetSymbolAddress((void**)&sc,   g_sc);
    cudaGetSymbolAddress((void**)&attn, g_attn);
    cudaGetSymbolAddress((void**)&h2,   g_h2);
    cudaGetSymbolAddress((void**)&h3,   g_h3);
    cudaGetSymbolAddress((void**)&gbuf, g_gate);
    cudaGetSymbolAddress((void**)&ubuf, g_up);

    const float scaling = 0.0625f;   // HEAD_DIM^-0.5 = 1/16

    // 1) rmsnorm(hidden, ln1) -> h
    rmsnorm_kernel<<<MTOK, 256>>>(hidden, ln1, h);

    // 2-4) QKV projections (NT: weight [N,K] row-major == col-major KxN)
    gemm_tf32_nt<<<dim3(HIDDEN / GBN, MTOK / GBM, 1), 256>>>(
        h, q_w, q, nullptr, HIDDEN, HIDDEN, HIDDEN, NH * HD,
        0, 0, 0, 0, 0, 0, 1, 1.0f);
    gemm_tf32_nt<<<dim3(HD / GBN, MTOK / GBM, 1), 256>>>(
        h, k_w, k, nullptr, HIDDEN, HIDDEN, HIDDEN, HD,
        0, 0, 0, 0, 0, 0, 1, 1.0f);
    gemm_tf32_nt<<<dim3(HD / GBN, MTOK / GBM, 1), 256>>>(
        h, v_w, v, nullptr, HIDDEN, HIDDEN, HIDDEN, HD,
        0, 0, 0, 0, 0, 0, 1, 1.0f);

    // 5-6) RoPE on q (8 heads) and k (1 head)
    {
        const long long tq = (long long)MTOK * NH * 128;
        rope_kernel<<<(unsigned)((tq + 255) / 256), 256>>>(q, fcos, fsin, NH, tq);
        const long long tk = (long long)MTOK * 128;
        rope_kernel<<<(unsigned)((tk + 255) / 256), 256>>>(k, fcos, fsin, 1, tk);
    }

    // 7) transpose V -> vt [b,d,c]
    transpose_v_kernel<<<dim3(SS / 32, HD / 32, BB), dim3(32, 32)>>>(v, vt);

    // 8) scores = (q . k^T) * scaling, batched over (b,h): M=S, N=S, K=HD
    gemm_tf32_nt<<<dim3(SS / GBN, SS / GBM, BB * NH), 256>>>(
        q, k, sc, nullptr, HD,
        NH * HD, HD, SS,
        (long long)SS * NH * HD, (long long)HD,      // A strides (b, h)
        (long long)SS * HD, 0,                       // B strides
        (long long)NH * SS * SS, (long long)SS * SS, // C strides
        NH, scaling);

    // 9) causal softmax
    softmax_causal_kernel<<<BB * NH * SS, 256>>>(sc);

    // 10) attn = probs . v  (NT with vt): M=S, N=HD, K=S
    gemm_tf32_nt<<<dim3(HD / GBN, SS / GBM, BB * NH), 256>>>(
        sc, vt, attn, nullptr, SS,
        SS, SS, NH * HD,
        (long long)NH * SS * SS, (long long)SS * SS, // A strides
        (long long)HD * SS, 0,                       // B strides
        (long long)SS * NH * HD, (long long)HD,      // C strides
        NH, 1.0f);

    // 11) h2 = hidden + attn . o_w^T
    gemm_tf32_nt<<<dim3(HIDDEN / GBN, MTOK / GBM, 1), 256>>>(
        attn, o_w, h2, hidden, NH * HD, NH * HD, NH * HD, HIDDEN,
        0, 0, 0, 0, 0, 0, 1, 1.0f);

    // 12) rmsnorm(h2, ln2) -> h3
    rmsnorm_kernel<<<MTOK, 256>>>(h2, ln2, h3);

    // 13-14) gate / up projections
    gemm_tf32_nt<<<dim3(INTER / GBN, MTOK / GBM, 1), 256>>>(
        h3, gate_w, gbuf, nullptr, HIDDEN, HIDDEN, HIDDEN, INTER,
        0, 0, 0, 0, 0, 0, 1, 1.0f);
    gemm_tf32_nt<<<dim3(INTER / GBN, MTOK / GBM, 1), 256>>>(
        h3, up_w, ubuf, nullptr, HIDDEN, HIDDEN, HIDDEN, INTER,
        0, 0, 0, 0, 0, 0, 1, 1.0f);

    // 15) gbuf = gelu(gbuf) * ubuf
    {
        const long long tot = (long long)MTOK * INTER;
        gelumul_kernel<<<(unsigned)((tot + 255) / 256), 256>>>(gbuf, ubuf, tot);
    }

    // 16) out = h2 + gbuf . down_w^T
    gemm_tf32_nt<<<dim3(HIDDEN / GBN, MTOK / GBM, 1), 256>>>(
        gbuf, down_w, out, h2, INTER, INTER, INTER, HIDDEN,
        0, 0, 0, 0, 0, 0, 1, 1.0f);
}

// round 7
// speedup vs baseline: 1.3137x; 1.3137x over previous
#include <cuda_runtime.h>
#include <cuda_bf16.h>
#include <cstdint>

// ---------------------------------------------------------------------------
// Problem constants
// ---------------------------------------------------------------------------
#define BB      2
#define SS      2048
#define HIDDEN  2048
#define NH      8
#define NKV     1
#define HD      256
#define INTER   16384
#define MTOK    (BB*SS)          // 4096 tokens
#define QKVN    (NH*HD + 2*HD)   // 2560 fused QKV output cols
#define KOFF    (NH*HD)          // 2048: k col offset in qkv
#define VOFF    (NH*HD + HD)     // 2304: v col offset in qkv

// ---------------------------------------------------------------------------
// Scratch (device globals; allocation inside kernel_launch is forbidden)
// ---------------------------------------------------------------------------
__device__ float g_h   [(size_t)MTOK * HIDDEN];          // normed hidden (ln1)
__device__ float g_wqkv[(size_t)QKVN * HIDDEN];          // fused qkv weight
__device__ float g_qkv [(size_t)MTOK * QKVN];            // fused qkv output
__device__ float g_vt  [(size_t)BB * HD * SS];           // v transposed [b,d,c]
__device__ float g_sc  [(size_t)BB * NH * SS * SS];      // scores/probs (268MB)
__device__ float g_attn[(size_t)MTOK * NH * HD];         // attn out [b,s,h,d]
__device__ float g_h2  [(size_t)MTOK * HIDDEN];          // hidden after attn+res
__device__ float g_h3  [(size_t)MTOK * HIDDEN];          // normed hidden (ln2)
__device__ float g_gate[(size_t)MTOK * INTER];           // gate (then gelu*up)
__device__ float g_up  [(size_t)MTOK * INTER];           // up

// ---------------------------------------------------------------------------
// Helpers
// ---------------------------------------------------------------------------
__device__ __forceinline__ unsigned f2tf(float x) {
    unsigned u;
    asm("cvt.rna.tf32.f32 %0, %1;" : "=r"(u) : "f"(x));
    return u;
}

__device__ __forceinline__ void cp_async16(float* sptr, const float* gptr) {
    unsigned sa = (unsigned)__cvta_generic_to_shared(sptr);
    asm volatile("cp.async.cg.shared.global [%0], [%1], 16;\n"
                 :: "r"(sa), "l"(gptr));
}
__device__ __forceinline__ void cp_commit() {
    asm volatile("cp.async.commit_group;\n");
}
__device__ __forceinline__ void cp_wait2() {
    asm volatile("cp.async.wait_group 2;\n");
}

// ---------------------------------------------------------------------------
// TF32 tensor-core NT GEMM:  C[m,n] = alpha * sum_k A[m,k]*B[n,k]  (+ addsrc)
// 128x128x16 tiles, 256 thr (8 warps, 64x32 warp tiles), mma m16n8k8 tf32.
// cp.async 4-stage pipeline into padded smem (GLD=20 floats: 80B row stride
// is 16B aligned for cp.async AND gives conflict-free fragment LDS).
// tf32 rounding (cvt.rna) applied on fragments after LDS (matches R5 math).
// Batched via blockIdx.z = zb*zInner + zh with independent strides.
// ---------------------------------------------------------------------------
#define GBM 128
#define GBN 128
#define GBK 16
#define GLD 20
#define STAGES 4
#define STAGE_F (GBM * GLD)                       // 2560 floats per mat/stage
#define GEMM_SMEM (STAGES * 2 * STAGE_F * 4)      // 81920 bytes

extern __shared__ float g_smem[];

__global__ __launch_bounds__(256, 2) void gemm_tf32_nt(
    const float* __restrict__ A, const float* __restrict__ B,
    float* __restrict__ C, const float* __restrict__ addsrc,
    int K, int lda, int ldb, int ldc,
    long long sAb, long long sAh,
    long long sBb, long long sBh,
    long long sCb, long long sCh,
    int zInner, float alpha)
{
    float* sA = g_smem;                       // STAGES * STAGE_F
    float* sB = g_smem + STAGES * STAGE_F;

    const int zb = blockIdx.z / zInner;
    const int zh = blockIdx.z % zInner;
    const float* Ab = A + zb * sAb + zh * sAh;
    const float* Bb = B + zb * sBb + zh * sBh;
    float*       Cb = C + zb * sCb + zh * sCh;
    const float* Db = addsrc ? (addsrc + zb * sCb + zh * sCh) : nullptr;

    const int m0  = blockIdx.y * GBM;
    const int n0  = blockIdx.x * GBN;
    const int tid = threadIdx.x;

    // Loader mapping: 1 float4 per thread per half-matrix per stage
    const int lr = tid >> 2;                  // 0..63
    const int lc = (tid & 3) << 2;            // 0,4,8,12
    const float* Ap0 = Ab + (long long)(m0 + lr) * lda + lc;
    const float* Ap1 = Ab + (long long)(m0 + lr + 64) * lda + lc;
    const float* Bp0 = Bb + (long long)(n0 + lr) * ldb + lc;
    const float* Bp1 = Bb + (long long)(n0 + lr + 64) * ldb + lc;
    const int soff0 = lr * GLD + lc;
    const int soff1 = (lr + 64) * GLD + lc;

    const int lane = tid & 31, warp = tid >> 5;
    const int wm = (warp >> 2) * 64;          // 0 / 64
    const int wn = (warp & 3) * 32;           // 0..96
    const int g  = lane >> 2, t4 = lane & 3;

    float acc[4][4][4];
#pragma unroll
    for (int i = 0; i < 4; i++)
#pragma unroll
        for (int j = 0; j < 4; j++)
#pragma unroll
            for (int r = 0; r < 4; r++) acc[i][j][r] = 0.f;

    const int nk = K / GBK;

    // Prologue: issue stages 0..2
#pragma unroll
    for (int s = 0; s < STAGES - 1; ++s) {
        if (s < nk) {
            const int ko = s * GBK;
            cp_async16(&sA[s * STAGE_F + soff0], Ap0 + ko);
            cp_async16(&sA[s * STAGE_F + soff1], Ap1 + ko);
            cp_async16(&sB[s * STAGE_F + soff0], Bp0 + ko);
            cp_async16(&sB[s * STAGE_F + soff1], Bp1 + ko);
        }
        cp_commit();
    }
    cp_wait2();
    __syncthreads();

    for (int t = 0; t < nk; ++t) {
        const int s = t & (STAGES - 1);

        // Issue stage t+3 (into buffer consumed at t-1; all warps synced since)
        const int tf = t + STAGES - 1;
        if (tf < nk) {
            const int sf = tf & (STAGES - 1);
            const int ko = tf * GBK;
            cp_async16(&sA[sf * STAGE_F + soff0], Ap0 + ko);
            cp_async16(&sA[sf * STAGE_F + soff1], Ap1 + ko);
            cp_async16(&sB[sf * STAGE_F + soff0], Bp0 + ko);
            cp_async16(&sB[sf * STAGE_F + soff1], Bp1 + ko);
        }
        cp_commit();

        const float* As_ = &sA[s * STAGE_F];
        const float* Bs_ = &sB[s * STAGE_F];

#pragma unroll
        for (int kk = 0; kk < GBK; kk += 8) {
            unsigned af[4][4];
            unsigned bf[4][2];
#pragma unroll
            for (int mi = 0; mi < 4; mi++) {
                const int r = wm + mi * 16 + g;
                af[mi][0] = f2tf(As_[r * GLD + kk + t4]);
                af[mi][1] = f2tf(As_[(r + 8) * GLD + kk + t4]);
                af[mi][2] = f2tf(As_[r * GLD + kk + t4 + 4]);
                af[mi][3] = f2tf(As_[(r + 8) * GLD + kk + t4 + 4]);
            }
#pragma unroll
            for (int ni = 0; ni < 4; ni++) {
                const int c = wn + ni * 8 + g;
                bf[ni][0] = f2tf(Bs_[c * GLD + kk + t4]);
                bf[ni][1] = f2tf(Bs_[c * GLD + kk + t4 + 4]);
            }
#pragma unroll
            for (int mi = 0; mi < 4; mi++)
#pragma unroll
                for (int ni = 0; ni < 4; ni++)
                    asm volatile(
                        "mma.sync.aligned.m16n8k8.row.col.f32.tf32.tf32.f32 "
                        "{%0,%1,%2,%3},{%4,%5,%6,%7},{%8,%9},{%0,%1,%2,%3};"
                        : "+f"(acc[mi][ni][0]), "+f"(acc[mi][ni][1]),
                          "+f"(acc[mi][ni][2]), "+f"(acc[mi][ni][3])
                        : "r"(af[mi][0]), "r"(af[mi][1]), "r"(af[mi][2]), "r"(af[mi][3]),
                          "r"(bf[ni][0]), "r"(bf[ni][1]));
        }

        cp_wait2();
        __syncthreads();
    }

    // Epilogue
#pragma unroll
    for (int mi = 0; mi < 4; mi++) {
#pragma unroll
        for (int ni = 0; ni < 4; ni++) {
            const int row = m0 + wm + mi * 16 + g;
            const int col = n0 + wn + ni * 8 + 2 * t4;
            const long long o1 = (long long)row * ldc + col;
            const long long o2 = o1 + (long long)8 * ldc;
            float v0 = alpha * acc[mi][ni][0];
            float v1 = alpha * acc[mi][ni][1];
            float v2 = alpha * acc[mi][ni][2];
            float v3 = alpha * acc[mi][ni][3];
            if (Db) {
                v0 += Db[o1]; v1 += Db[o1 + 1];
                v2 += Db[o2]; v3 += Db[o2 + 1];
            }
            Cb[o1] = v0; Cb[o1 + 1] = v1;
            Cb[o2] = v2; Cb[o2 + 1] = v3;
        }
    }
}

// ---------------------------------------------------------------------------
// RMSNorm: one block per row of 2048
// ---------------------------------------------------------------------------
__global__ __launch_bounds__(256) void rmsnorm_kernel(
    const float* __restrict__ x, const float* __restrict__ w,
    float* __restrict__ o)
{
    const long long row = blockIdx.x;
    const float* xr = x + row * HIDDEN;
    float* orow = o + row * HIDDEN;

    float ss = 0.f;
    for (int i = threadIdx.x; i < HIDDEN; i += 256) {
        const float v = xr[i];
        ss = fmaf(v, v, ss);
    }
#pragma unroll
    for (int off = 16; off; off >>= 1) ss += __shfl_xor_sync(~0u, ss, off);

    __shared__ float sred[8];
    const int wi = threadIdx.x >> 5, li = threadIdx.x & 31;
    if (li == 0) sred[wi] = ss;
    __syncthreads();
    float tot = 0.f;
#pragma unroll
    for (int i = 0; i < 8; i++) tot += sred[i];

    const float rs = rsqrtf(tot * (1.0f / HIDDEN) + 1e-6f);
    for (int i = threadIdx.x; i < HIDDEN; i += 256)
        orow[i] = xr[i] * rs * (1.0f + w[i]);
}

// ---------------------------------------------------------------------------
// RoPE (in place): token rows with arbitrary stride, nheads heads of 256
// ---------------------------------------------------------------------------
__global__ void rope_kernel(float* __restrict__ x,
                            const float* __restrict__ cs,
                            const float* __restrict__ sn,
                            int nheads, int tok_stride, long long total)
{
    const long long idx = (long long)blockIdx.x * blockDim.x + threadIdx.x;
    if (idx >= total) return;
    const int i = (int)(idx & 127);
    const long long t = idx >> 7;            // b*S*nheads + s*nheads + h
    const int h = (int)(t % nheads);
    const long long bs = t / nheads;         // b*S + s
    const int s = (int)(bs & (SS - 1));
    const float c = cs[s * 128 + i];
    const float si = sn[s * 128 + i];
    float* p = x + bs * tok_stride + h * HD;
    const float x1 = p[i];
    const float x2 = p[i + 128];
    p[i]       = x1 * c - x2 * si;
    p[i + 128] = x1 * si + x2 * c;
}

// ---------------------------------------------------------------------------
// Transpose V: [b, c(2048), d(256)] (row stride QKVN) -> [b, d, c]
// ---------------------------------------------------------------------------
__global__ void transpose_v_kernel(const float* __restrict__ v,
                                   float* __restrict__ vt)
{
    __shared__ float tile[32][33];
    const int b = blockIdx.z;
    const int c0 = blockIdx.x * 32;
    const int d0 = blockIdx.y * 32;
    const float* vb = v + (long long)b * SS * QKVN;
    float* vtb = vt + (long long)b * HD * SS;
    const int tx = threadIdx.x, ty = threadIdx.y;
    tile[ty][tx] = vb[(long long)(c0 + ty) * QKVN + d0 + tx];
    __syncthreads();
    vtb[(long long)(d0 + ty) * SS + c0 + tx] = tile[tx][ty];
}

// ---------------------------------------------------------------------------
// Causal softmax over rows of [B*H, S, S]
// ---------------------------------------------------------------------------
__global__ __launch_bounds__(256) void softmax_causal_kernel(float* __restrict__ sc)
{
    const long long rowid = blockIdx.x;            // 0 .. B*H*S-1
    const int s = (int)(rowid & (SS - 1));
    float* row = sc + rowid * SS;
    const int n = s + 1;

    float mx = -3.4e38f;
    for (int i = threadIdx.x; i < n; i += 256) mx = fmaxf(mx, row[i]);
#pragma unroll
    for (int off = 16; off; off >>= 1) mx = fmaxf(mx, __shfl_xor_sync(~0u, mx, off));

    __shared__ float sm[8], ssum[8];
    const int wi = threadIdx.x >> 5, li = threadIdx.x & 31;
    if (li == 0) sm[wi] = mx;
    __syncthreads();
    float m2 = -3.4e38f;
#pragma unroll
    for (int i = 0; i < 8; i++) m2 = fmaxf(m2, sm[i]);

    float sum = 0.f;
    for (int i = threadIdx.x; i < n; i += 256) sum += __expf(row[i] - m2);
#pragma unroll
    for (int off = 16; off; off >>= 1) sum += __shfl_xor_sync(~0u, sum, off);
    if (li == 0) ssum[wi] = sum;
    __syncthreads();
    float tot = 0.f;
#pragma unroll
    for (int i = 0; i < 8; i++) tot += ssum[i];
    const float inv = 1.0f / tot;

    for (int i = threadIdx.x; i < SS; i += 256)
        row[i] = (i < n) ? __expf(row[i] - m2) * inv : 0.f;
}

// ---------------------------------------------------------------------------
// gate = gelu_tanh(gate) * up
// ---------------------------------------------------------------------------
__global__ void gelumul_kernel(float* __restrict__ gate,
                               const float* __restrict__ up,
                               long long total)
{
    const long long i = (long long)blockIdx.x * blockDim.x + threadIdx.x;
    if (i >= total) return;
    const float x = gate[i];
    const float x3 = x * x * x;
    const float t = tanhf(0.7978845608028654f * (x + 0.044715f * x3));
    gate[i] = 0.5f * x * (1.0f + t) * up[i];
}

// ---------------------------------------------------------------------------
// Launch
// ---------------------------------------------------------------------------
extern "C" void kernel_launch(void* const* d_in, const int* in_sizes, int n_in,
                              void* d_out, int out_size)
{
    (void)in_sizes; (void)n_in; (void)out_size;

    const float* hidden = (const float*)d_in[0];
    const float* fcos   = (const float*)d_in[1];
    const float* fsin   = (const float*)d_in[2];
    // d_in[3..6] (kv indices / zero caches / causal mask) unused by construction.
    const float* q_w    = (const float*)d_in[7];
    const float* k_w    = (const float*)d_in[8];
    const float* v_w    = (const float*)d_in[9];
    const float* o_w    = (const float*)d_in[10];
    const float* gate_w = (const float*)d_in[11];
    const float* up_w   = (const float*)d_in[12];
    const float* down_w = (const float*)d_in[13];
    const float* ln1    = (const float*)d_in[14];
    const float* ln2    = (const float*)d_in[15];
    float* out = (float*)d_out;

    float *h, *wqkv, *qkv, *vt, *sc, *attn, *h2, *h3, *gbuf, *ubuf;
    cudaGetSymbolAddress((void**)&h,    g_h);
    cudaGetSymbolAddress((void**)&wqkv, g_wqkv);
    cudaGetSymbolAddress((void**)&qkv,  g_qkv);
    cudaGetSymbolAddress((void**)&vt,   g_vt);
    cudaGetSymbolAddress((void**)&sc,   g_sc);
    cudaGetSymbolAddress((void**)&attn, g_attn);
    cudaGetSymbolAddress((void**)&h2,   g_h2);
    cudaGetSymbolAddress((void**)&h3,   g_h3);
    cudaGetSymbolAddress((void**)&gbuf, g_gate);
    cudaGetSymbolAddress((void**)&ubuf, g_up);

    cudaFuncSetAttribute(gemm_tf32_nt,
                         cudaFuncAttributeMaxDynamicSharedMemorySize, GEMM_SMEM);

    const float scaling = 0.0625f;   // HEAD_DIM^-0.5 = 1/16

    // 0) concatenate q/k/v weights into one [2560, 2048] matrix
    cudaMemcpyAsync(wqkv,                     q_w, (size_t)KOFF * HIDDEN * 4,
                    cudaMemcpyDeviceToDevice, 0);
    cudaMemcpyAsync(wqkv + (size_t)KOFF * HIDDEN, k_w, (size_t)HD * HIDDEN * 4,
                    cudaMemcpyDeviceToDevice, 0);
    cudaMemcpyAsync(wqkv + (size_t)VOFF * HIDDEN, v_w, (size_t)HD * HIDDEN * 4,
                    cudaMemcpyDeviceToDevice, 0);

    // 1) rmsnorm(hidden, ln1) -> h
    rmsnorm_kernel<<<MTOK, 256>>>(hidden, ln1, h);

    // 2) fused QKV projection: [4096,2048] x [2560,2048]^T -> qkv [4096,2560]
    gemm_tf32_nt<<<dim3(QKVN / GBN, MTOK / GBM, 1), 256, GEMM_SMEM>>>(
        h, wqkv, qkv, nullptr, HIDDEN, HIDDEN, HIDDEN, QKVN,
        0, 0, 0, 0, 0, 0, 1, 1.0f);

    // 3) RoPE on q (8 heads) and k (1 head), in place inside qkv
    {
        const long long tq = (long long)MTOK * NH * 128;
        rope_kernel<<<(unsigned)((tq + 255) / 256), 256>>>(
            qkv, fcos, fsin, NH, QKVN, tq);
        const long long tk = (long long)MTOK * 128;
        rope_kernel<<<(unsigned)((tk + 255) / 256), 256>>>(
            qkv + KOFF, fcos, fsin, 1, QKVN, tk);
    }

    // 4) transpose V -> vt [b,d,c]
    transpose_v_kernel<<<dim3(SS / 32, HD / 32, BB), dim3(32, 32)>>>(
        qkv + VOFF, vt);

    // 5) scores = (q . k^T) * scaling, batched over (b,h): M=S, N=S, K=HD
    gemm_tf32_nt<<<dim3(SS / GBN, SS / GBM, BB * NH), 256, GEMM_SMEM>>>(
        qkv, qkv + KOFF, sc, nullptr, HD,
        QKVN, QKVN, SS,
        (long long)SS * QKVN, (long long)HD,         // A strides (b, h)
        (long long)SS * QKVN, 0,                     // B strides
        (long long)NH * SS * SS, (long long)SS * SS, // C strides
        NH, scaling);

    // 6) causal softmax
    softmax_causal_kernel<<<BB * NH * SS, 256>>>(sc);

    // 7) attn = probs . v  (NT with vt): M=S, N=HD, K=S
    gemm_tf32_nt<<<dim3(HD / GBN, SS / GBM, BB * NH), 256, GEMM_SMEM>>>(
        sc, vt, attn, nullptr, SS,
        SS, SS, NH * HD,
        (long long)NH * SS * SS, (long long)SS * SS, // A strides
        (long long)HD * SS, 0,                       // B strides
        (long long)SS * NH * HD, (long long)HD,      // C strides
        NH, 1.0f);

    // 8) h2 = hidden + attn . o_w^T
    gemm_tf32_nt<<<dim3(HIDDEN / GBN, MTOK / GBM, 1), 256, GEMM_SMEM>>>(
        attn, o_w, h2, hidden, NH * HD, NH * HD, NH * HD, HIDDEN,
        0, 0, 0, 0, 0, 0, 1, 1.0f);

    // 9) rmsnorm(h2, ln2) -> h3
    rmsnorm_kernel<<<MTOK, 256>>>(h2, ln2, h3);

    // 10-11) gate / up projections
    gemm_tf32_nt<<<dim3(INTER / GBN, MTOK / GBM, 1), 256, GEMM_SMEM>>>(
        h3, gate_w, gbuf, nullptr, HIDDEN, HIDDEN, HIDDEN, INTER,
        0, 0, 0, 0, 0, 0, 1, 1.0f);
    gemm_tf32_nt<<<dim3(INTER / GBN, MTOK / GBM, 1), 256, GEMM_SMEM>>>(
        h3, up_w, ubuf, nullptr, HIDDEN, HIDDEN, HIDDEN, INTER,
        0, 0, 0, 0, 0, 0, 1, 1.0f);

    // 12) gbuf = gelu(gbuf) * ubuf
    {
        const long long tot = (long long)MTOK * INTER;
        gelumul_kernel<<<(unsigned)((tot + 255) / 256), 256>>>(gbuf, ubuf, tot);
    }

    // 13) out = h2 + gbuf . down_w^T
    gemm_tf32_nt<<<dim3(HIDDEN / GBN, MTOK / GBM, 1), 256, GEMM_SMEM>>>(
        gbuf, down_w, out, h2, INTER, INTER, INTER, HIDDEN,
        0, 0, 0, 0, 0, 0, 1, 1.0f);
}

// round 8
// speedup vs baseline: 1.3929x; 1.0602x over previous
#include <cuda_runtime.h>
#include <cuda_bf16.h>
#include <cstdint>

// ---------------------------------------------------------------------------
// Problem constants
// ---------------------------------------------------------------------------
#define BB      2
#define SS      2048
#define HIDDEN  2048
#define NH      8
#define NKV     1
#define HD      256
#define INTER   16384
#define MTOK    (BB*SS)          // 4096 tokens
#define QKVN    (NH*HD + 2*HD)   // 2560 fused QKV output cols
#define KOFF    (NH*HD)          // 2048: k col offset in qkv
#define VOFF    (NH*HD + HD)     // 2304: v col offset in qkv

// ---------------------------------------------------------------------------
// Scratch
// ---------------------------------------------------------------------------
__device__ float g_h   [(size_t)MTOK * HIDDEN];
__device__ float g_wqkv[(size_t)QKVN * HIDDEN];
__device__ float g_qkv [(size_t)MTOK * QKVN];
__device__ float g_vt  [(size_t)BB * HD * SS];
__device__ float g_sc  [(size_t)BB * NH * SS * SS];
__device__ float g_attn[(size_t)MTOK * NH * HD];
__device__ float g_h2  [(size_t)MTOK * HIDDEN];
__device__ float g_h3  [(size_t)MTOK * HIDDEN];
__device__ float g_gate[(size_t)MTOK * INTER];
__device__ float g_up  [(size_t)MTOK * INTER];

// ---------------------------------------------------------------------------
// Helpers
// ---------------------------------------------------------------------------
__device__ __forceinline__ unsigned f2tf(float x) {
    unsigned u;
    asm("cvt.rna.tf32.f32 %0, %1;" : "=r"(u) : "f"(x));
    return u;
}
__device__ __forceinline__ float roundtf(float x) {
    return __uint_as_float(f2tf(x));
}

__device__ __forceinline__ void cp_async16(float* sptr, const float* gptr) {
    unsigned sa = (unsigned)__cvta_generic_to_shared(sptr);
    asm volatile("cp.async.cg.shared.global [%0], [%1], 16;\n"
                 :: "r"(sa), "l"(gptr));
}
__device__ __forceinline__ void cp_commit() {
    asm volatile("cp.async.commit_group;\n");
}
__device__ __forceinline__ void cp_wait2() {
    asm volatile("cp.async.wait_group 2;\n");
}

__device__ __forceinline__ void ldsm4(unsigned& r0, unsigned& r1,
                                      unsigned& r2, unsigned& r3, unsigned sa) {
    asm volatile("ldmatrix.sync.aligned.m8n8.x4.shared.b16 {%0,%1,%2,%3}, [%4];"
                 : "=r"(r0), "=r"(r1), "=r"(r2), "=r"(r3) : "r"(sa));
}

// ---------------------------------------------------------------------------
// TF32 NT GEMM, 128x128x16 tiles, 8 warps (64x32 warp tiles), 4-stage cp.async,
// ldmatrix fragment loads. A operands must be pre-rounded to tf32 in gmem.
// CVTB: round B fragments in-loop (for raw fp32 weights).
// ROUNDC: round outputs to tf32 (when C feeds a later GEMM as A).
// ---------------------------------------------------------------------------
#define GBM 128
#define GBN 128
#define GBK 16
#define GLD 20
#define STAGES 4
#define STAGE_F (GBM * GLD)                       // 2560 floats per mat/stage
#define GEMM_SMEM (STAGES * 2 * STAGE_F * 4)      // 81920 bytes

extern __shared__ float g_smem[];

template<bool CVTB, bool ROUNDC>
__global__ __launch_bounds__(256, 2) void gemm_tf32_nt(
    const float* __restrict__ A, const float* __restrict__ B,
    float* __restrict__ C, const float* __restrict__ addsrc,
    int K, int lda, int ldb, int ldc,
    long long sAb, long long sAh,
    long long sBb, long long sBh,
    long long sCb, long long sCh,
    int zInner, float alpha)
{
    float* sA = g_smem;
    float* sB = g_smem + STAGES * STAGE_F;

    const int zb = blockIdx.z / zInner;
    const int zh = blockIdx.z % zInner;
    const float* Ab = A + zb * sAb + zh * sAh;
    const float* Bb = B + zb * sBb + zh * sBh;
    float*       Cb = C + zb * sCb + zh * sCh;
    const float* Db = addsrc ? (addsrc + zb * sCb + zh * sCh) : nullptr;

    const int m0  = blockIdx.y * GBM;
    const int n0  = blockIdx.x * GBN;
    const int tid = threadIdx.x;

    // cp.async loader mapping: 1 float4 per thread per half-matrix per stage
    const int lr = tid >> 2;                  // 0..63
    const int lc = (tid & 3) << 2;            // 0,4,8,12
    const float* Ap0 = Ab + (long long)(m0 + lr) * lda + lc;
    const float* Ap1 = Ab + (long long)(m0 + lr + 64) * lda + lc;
    const float* Bp0 = Bb + (long long)(n0 + lr) * ldb + lc;
    const float* Bp1 = Bb + (long long)(n0 + lr + 64) * ldb + lc;
    const int soff0 = lr * GLD + lc;
    const int soff1 = (lr + 64) * GLD + lc;

    const int lane = tid & 31, warp = tid >> 5;
    const int wm = (warp >> 2) * 64;          // 0 / 64
    const int wn = (warp & 3) * 32;           // 0..96
    const int g  = lane >> 2, t4 = lane & 3;

    // ldmatrix per-lane addressing (byte offsets within a stage)
    // A tile (mi): rows wm+mi*16+(L&15), k = kk + (L>>4)*4
    const int aRow = wm + (lane & 15);
    const int aK   = (lane >> 4) << 2;        // 0 or 4
    // B pair (covers ni=2p, 2p+1): rows wn+p*16+(L&7)+((L>>4)<<3), k = kk+((L>>3)&1)*4
    const int bRow = wn + (lane & 7) + ((lane >> 4) << 3);
    const int bK   = ((lane >> 3) & 1) << 2;  // 0 or 4

    const unsigned sbase  = (unsigned)__cvta_generic_to_shared(g_smem);
    const unsigned sBbase = sbase + (unsigned)(STAGES * STAGE_F) * 4u;

    float acc[4][4][4];
#pragma unroll
    for (int i = 0; i < 4; i++)
#pragma unroll
        for (int j = 0; j < 4; j++)
#pragma unroll
            for (int r = 0; r < 4; r++) acc[i][j][r] = 0.f;

    const int nk = K / GBK;

    // Prologue: issue stages 0..2
#pragma unroll
    for (int s = 0; s < STAGES - 1; ++s) {
        if (s < nk) {
            const int ko = s * GBK;
            cp_async16(&sA[s * STAGE_F + soff0], Ap0 + ko);
            cp_async16(&sA[s * STAGE_F + soff1], Ap1 + ko);
            cp_async16(&sB[s * STAGE_F + soff0], Bp0 + ko);
            cp_async16(&sB[s * STAGE_F + soff1], Bp1 + ko);
        }
        cp_commit();
    }
    cp_wait2();
    __syncthreads();

    for (int t = 0; t < nk; ++t) {
        const int s = t & (STAGES - 1);

        const int tf = t + STAGES - 1;
        if (tf < nk) {
            const int sf = tf & (STAGES - 1);
            const int ko = tf * GBK;
            cp_async16(&sA[sf * STAGE_F + soff0], Ap0 + ko);
            cp_async16(&sA[sf * STAGE_F + soff1], Ap1 + ko);
            cp_async16(&sB[sf * STAGE_F + soff0], Bp0 + ko);
            cp_async16(&sB[sf * STAGE_F + soff1], Bp1 + ko);
        }
        cp_commit();

        const unsigned aSt = sbase  + (unsigned)(s * STAGE_F) * 4u;
        const unsigned bSt = sBbase + (unsigned)(s * STAGE_F) * 4u;

#pragma unroll
        for (int kk = 0; kk < GBK; kk += 8) {
            unsigned af[4][4];
            unsigned bf[4][2];
#pragma unroll
            for (int mi = 0; mi < 4; mi++) {
                const unsigned addr =
                    aSt + (unsigned)(((aRow + mi * 16) * GLD) + kk + aK) * 4u;
                ldsm4(af[mi][0], af[mi][1], af[mi][2], af[mi][3], addr);
            }
#pragma unroll
            for (int p = 0; p < 2; p++) {
                const unsigned addr =
                    bSt + (unsigned)(((bRow + p * 16) * GLD) + kk + bK) * 4u;
                ldsm4(bf[2 * p][0], bf[2 * p][1], bf[2 * p + 1][0], bf[2 * p + 1][1], addr);
            }
            if (CVTB) {
#pragma unroll
                for (int ni = 0; ni < 4; ni++) {
                    bf[ni][0] = f2tf(__uint_as_float(bf[ni][0]));
                    bf[ni][1] = f2tf(__uint_as_float(bf[ni][1]));
                }
            }
#pragma unroll
            for (int mi = 0; mi < 4; mi++)
#pragma unroll
                for (int ni = 0; ni < 4; ni++)
                    asm volatile(
                        "mma.sync.aligned.m16n8k8.row.col.f32.tf32.tf32.f32 "
                        "{%0,%1,%2,%3},{%4,%5,%6,%7},{%8,%9},{%0,%1,%2,%3};"
                        : "+f"(acc[mi][ni][0]), "+f"(acc[mi][ni][1]),
                          "+f"(acc[mi][ni][2]), "+f"(acc[mi][ni][3])
                        : "r"(af[mi][0]), "r"(af[mi][1]), "r"(af[mi][2]), "r"(af[mi][3]),
                          "r"(bf[ni][0]), "r"(bf[ni][1]));
        }

        cp_wait2();
        __syncthreads();
    }

    // Epilogue
#pragma unroll
    for (int mi = 0; mi < 4; mi++) {
#pragma unroll
        for (int ni = 0; ni < 4; ni++) {
            const int row = m0 + wm + mi * 16 + g;
            const int col = n0 + wn + ni * 8 + 2 * t4;
            const long long o1 = (long long)row * ldc + col;
            const long long o2 = o1 + (long long)8 * ldc;
            float v0 = alpha * acc[mi][ni][0];
            float v1 = alpha * acc[mi][ni][1];
            float v2 = alpha * acc[mi][ni][2];
            float v3 = alpha * acc[mi][ni][3];
            if (Db) {
                v0 += Db[o1]; v1 += Db[o1 + 1];
                v2 += Db[o2]; v3 += Db[o2 + 1];
            }
            if (ROUNDC) {
                v0 = roundtf(v0); v1 = roundtf(v1);
                v2 = roundtf(v2); v3 = roundtf(v3);
            }
            Cb[o1] = v0; Cb[o1 + 1] = v1;
            Cb[o2] = v2; Cb[o2 + 1] = v3;
        }
    }
}

// ---------------------------------------------------------------------------
// RMSNorm (output rounded to tf32 — it is consumed only as GEMM A operand)
// ---------------------------------------------------------------------------
__global__ __launch_bounds__(256) void rmsnorm_kernel(
    const float* __restrict__ x, const float* __restrict__ w,
    float* __restrict__ o)
{
    const long long row = blockIdx.x;
    const float* xr = x + row * HIDDEN;
    float* orow = o + row * HIDDEN;

    float ss = 0.f;
    for (int i = threadIdx.x; i < HIDDEN; i += 256) {
        const float v = xr[i];
        ss = fmaf(v, v, ss);
    }
#pragma unroll
    for (int off = 16; off; off >>= 1) ss += __shfl_xor_sync(~0u, ss, off);

    __shared__ float sred[8];
    const int wi = threadIdx.x >> 5, li = threadIdx.x & 31;
    if (li == 0) sred[wi] = ss;
    __syncthreads();
    float tot = 0.f;
#pragma unroll
    for (int i = 0; i < 8; i++) tot += sred[i];

    const float rs = rsqrtf(tot * (1.0f / HIDDEN) + 1e-6f);
    for (int i = threadIdx.x; i < HIDDEN; i += 256)
        orow[i] = roundtf(xr[i] * rs * (1.0f + w[i]));
}

// ---------------------------------------------------------------------------
// RoPE (in place, writes tf32-rounded)
// ---------------------------------------------------------------------------
__global__ void rope_kernel(float* __restrict__ x,
                            const float* __restrict__ cs,
                            const float* __restrict__ sn,
                            int nheads, int tok_stride, long long total)
{
    const long long idx = (long long)blockIdx.x * blockDim.x + threadIdx.x;
    if (idx >= total) return;
    const int i = (int)(idx & 127);
    const long long t = idx >> 7;
    const int h = (int)(t % nheads);
    const long long bs = t / nheads;
    const int s = (int)(bs & (SS - 1));
    const float c = cs[s * 128 + i];
    const float si = sn[s * 128 + i];
    float* p = x + bs * tok_stride + h * HD;
    const float x1 = p[i];
    const float x2 = p[i + 128];
    p[i]       = roundtf(x1 * c - x2 * si);
    p[i + 128] = roundtf(x1 * si + x2 * c);
}

// ---------------------------------------------------------------------------
// Transpose V (writes tf32-rounded)
// ---------------------------------------------------------------------------
__global__ void transpose_v_kernel(const float* __restrict__ v,
                                   float* __restrict__ vt)
{
    __shared__ float tile[32][33];
    const int b = blockIdx.z;
    const int c0 = blockIdx.x * 32;
    const int d0 = blockIdx.y * 32;
    const float* vb = v + (long long)b * SS * QKVN;
    float* vtb = vt + (long long)b * HD * SS;
    const int tx = threadIdx.x, ty = threadIdx.y;
    tile[ty][tx] = vb[(long long)(c0 + ty) * QKVN + d0 + tx];
    __syncthreads();
    vtb[(long long)(d0 + ty) * SS + c0 + tx] = roundtf(tile[tx][ty]);
}

// ---------------------------------------------------------------------------
// Causal softmax (writes tf32-rounded probabilities)
// ---------------------------------------------------------------------------
__global__ __launch_bounds__(256) void softmax_causal_kernel(float* __restrict__ sc)
{
    const long long rowid = blockIdx.x;
    const int s = (int)(rowid & (SS - 1));
    float* row = sc + rowid * SS;
    const int n = s + 1;

    float mx = -3.4e38f;
    for (int i = threadIdx.x; i < n; i += 256) mx = fmaxf(mx, row[i]);
#pragma unroll
    for (int off = 16; off; off >>= 1) mx = fmaxf(mx, __shfl_xor_sync(~0u, mx, off));

    __shared__ float sm[8], ssum[8];
    const int wi = threadIdx.x >> 5, li = threadIdx.x & 31;
    if (li == 0) sm[wi] = mx;
    __syncthreads();
    float m2 = -3.4e38f;
#pragma unroll
    for (int i = 0; i < 8; i++) m2 = fmaxf(m2, sm[i]);

    float sum = 0.f;
    for (int i = threadIdx.x; i < n; i += 256) sum += __expf(row[i] - m2);
#pragma unroll
    for (int off = 16; off; off >>= 1) sum += __shfl_xor_sync(~0u, sum, off);
    if (li == 0) ssum[wi] = sum;
    __syncthreads();
    float tot = 0.f;
#pragma unroll
    for (int i = 0; i < 8; i++) tot += ssum[i];
    const float inv = 1.0f / tot;

    for (int i = threadIdx.x; i < SS; i += 256)
        row[i] = (i < n) ? roundtf(__expf(row[i] - m2) * inv) : 0.f;
}

// ---------------------------------------------------------------------------
// gate = gelu_tanh(gate) * up (writes tf32-rounded)
// ---------------------------------------------------------------------------
__global__ void gelumul_kernel(float* __restrict__ gate,
                               const float* __restrict__ up,
                               long long total)
{
    const long long i = (long long)blockIdx.x * blockDim.x + threadIdx.x;
    if (i >= total) return;
    const float x = gate[i];
    const float x3 = x * x * x;
    const float t = tanhf(0.7978845608028654f * (x + 0.044715f * x3));
    gate[i] = roundtf(0.5f * x * (1.0f + t) * up[i]);
}

// ---------------------------------------------------------------------------
// Launch
// ---------------------------------------------------------------------------
extern "C" void kernel_launch(void* const* d_in, const int* in_sizes, int n_in,
                              void* d_out, int out_size)
{
    (void)in_sizes; (void)n_in; (void)out_size;

    const float* hidden = (const float*)d_in[0];
    const float* fcos   = (const float*)d_in[1];
    const float* fsin   = (const float*)d_in[2];
    const float* q_w    = (const float*)d_in[7];
    const float* k_w    = (const float*)d_in[8];
    const float* v_w    = (const float*)d_in[9];
    const float* o_w    = (const float*)d_in[10];
    const float* gate_w = (const float*)d_in[11];
    const float* up_w   = (const float*)d_in[12];
    const float* down_w = (const float*)d_in[13];
    const float* ln1    = (const float*)d_in[14];
    const float* ln2    = (const float*)d_in[15];
    float* out = (float*)d_out;

    float *h, *wqkv, *qkv, *vt, *sc, *attn, *h2, *h3, *gbuf, *ubuf;
    cudaGetSymbolAddress((void**)&h,    g_h);
    cudaGetSymbolAddress((void**)&wqkv, g_wqkv);
    cudaGetSymbolAddress((void**)&qkv,  g_qkv);
    cudaGetSymbolAddress((void**)&vt,   g_vt);
    cudaGetSymbolAddress((void**)&sc,   g_sc);
    cudaGetSymbolAddress((void**)&attn, g_attn);
    cudaGetSymbolAddress((void**)&h2,   g_h2);
    cudaGetSymbolAddress((void**)&h3,   g_h3);
    cudaGetSymbolAddress((void**)&gbuf, g_gate);
    cudaGetSymbolAddress((void**)&ubuf, g_up);

    cudaFuncSetAttribute(gemm_tf32_nt<true,  false>,
                         cudaFuncAttributeMaxDynamicSharedMemorySize, GEMM_SMEM);
    cudaFuncSetAttribute(gemm_tf32_nt<false, false>,
                         cudaFuncAttributeMaxDynamicSharedMemorySize, GEMM_SMEM);
    cudaFuncSetAttribute(gemm_tf32_nt<false, true>,
                         cudaFuncAttributeMaxDynamicSharedMemorySize, GEMM_SMEM);

    const float scaling = 0.0625f;   // HEAD_DIM^-0.5 = 1/16

    // 0) concatenate q/k/v weights into one [2560, 2048] matrix
    cudaMemcpyAsync(wqkv,                         q_w, (size_t)KOFF * HIDDEN * 4,
                    cudaMemcpyDeviceToDevice, 0);
    cudaMemcpyAsync(wqkv + (size_t)KOFF * HIDDEN, k_w, (size_t)HD * HIDDEN * 4,
                    cudaMemcpyDeviceToDevice, 0);
    cudaMemcpyAsync(wqkv + (size_t)VOFF * HIDDEN, v_w, (size_t)HD * HIDDEN * 4,
                    cudaMemcpyDeviceToDevice, 0);

    // 1) rmsnorm(hidden, ln1) -> h (tf32-rounded)
    rmsnorm_kernel<<<MTOK, 256>>>(hidden, ln1, h);

    // 2) fused QKV projection
    gemm_tf32_nt<true, false><<<dim3(QKVN / GBN, MTOK / GBM, 1), 256, GEMM_SMEM>>>(
        h, wqkv, qkv, nullptr, HIDDEN, HIDDEN, HIDDEN, QKVN,
        0, 0, 0, 0, 0, 0, 1, 1.0f);

    // 3) RoPE on q and k (rounds in place)
    {
        const long long tq = (long long)MTOK * NH * 128;
        rope_kernel<<<(unsigned)((tq + 255) / 256), 256>>>(
            qkv, fcos, fsin, NH, QKVN, tq);
        const long long tk = (long long)MTOK * 128;
        rope_kernel<<<(unsigned)((tk + 255) / 256), 256>>>(
            qkv + KOFF, fcos, fsin, 1, QKVN, tk);
    }

    // 4) transpose V -> vt (rounds)
    transpose_v_kernel<<<dim3(SS / 32, HD / 32, BB), dim3(32, 32)>>>(
        qkv + VOFF, vt);

    // 5) scores = (q . k^T) * scaling (both operands pre-rounded)
    gemm_tf32_nt<false, false><<<dim3(SS / GBN, SS / GBM, BB * NH), 256, GEMM_SMEM>>>(
        qkv, qkv + KOFF, sc, nullptr, HD,
        QKVN, QKVN, SS,
        (long long)SS * QKVN, (long long)HD,
        (long long)SS * QKVN, 0,
        (long long)NH * SS * SS, (long long)SS * SS,
        NH, scaling);

    // 6) causal softmax (rounds probs)
    softmax_causal_kernel<<<BB * NH * SS, 256>>>(sc);

    // 7) attn = probs . v (pre-rounded inputs; round output for O-proj)
    gemm_tf32_nt<false, true><<<dim3(HD / GBN, SS / GBM, BB * NH), 256, GEMM_SMEM>>>(
        sc, vt, attn, nullptr, SS,
        SS, SS, NH * HD,
        (long long)NH * SS * SS, (long long)SS * SS,
        (long long)HD * SS, 0,
        (long long)SS * NH * HD, (long long)HD,
        NH, 1.0f);

    // 8) h2 = hidden + attn . o_w^T
    gemm_tf32_nt<true, false><<<dim3(HIDDEN / GBN, MTOK / GBM, 1), 256, GEMM_SMEM>>>(
        attn, o_w, h2, hidden, NH * HD, NH * HD, NH * HD, HIDDEN,
        0, 0, 0, 0, 0, 0, 1, 1.0f);

    // 9) rmsnorm(h2, ln2) -> h3 (rounded)
    rmsnorm_kernel<<<MTOK, 256>>>(h2, ln2, h3);

    // 10-11) gate / up projections
    gemm_tf32_nt<true, false><<<dim3(INTER / GBN, MTOK / GBM, 1), 256, GEMM_SMEM>>>(
        h3, gate_w, gbuf, nullptr, HIDDEN, HIDDEN, HIDDEN, INTER,
        0, 0, 0, 0, 0, 0, 1, 1.0f);
    gemm_tf32_nt<true, false><<<dim3(INTER / GBN, MTOK / GBM, 1), 256, GEMM_SMEM>>>(
        h3, up_w, ubuf, nullptr, HIDDEN, HIDDEN, HIDDEN, INTER,
        0, 0, 0, 0, 0, 0, 1, 1.0f);

    // 12) gbuf = gelu(gbuf) * ubuf (rounded)
    {
        const long long tot = (long long)MTOK * INTER;
        gelumul_kernel<<<(unsigned)((tot + 255) / 256), 256>>>(gbuf, ubuf, tot);
    }

    // 13) out = h2 + gbuf . down_w^T
    gemm_tf32_nt<true, false><<<dim3(HIDDEN / GBN, MTOK / GBM, 1), 256, GEMM_SMEM>>>(
        gbuf, down_w, out, h2, INTER, INTER, INTER, HIDDEN,
        0, 0, 0, 0, 0, 0, 1, 1.0f);
}